// round 10
// baseline (speedup 1.0000x reference)
#include <cuda_runtime.h>

typedef unsigned long long u64;

__device__ float g_h2[32768 * 32];
__device__ float g_ldp[16 * 32768];
__device__ float g_w3m[64 * 768];
__device__ float g_b3t[64 * 24];

__device__ __forceinline__ void fma2(u64 &acc, u64 a, u64 b){
  asm("fma.rn.f32x2 %0, %1, %2, %0;" : "+l"(acc) : "l"(a), "l"(b));
}
__device__ __forceinline__ float2 unpk(u64 v){
  float2 f; asm("mov.b64 {%0,%1}, %2;" : "=f"(f.x), "=f"(f.y) : "l"(v)); return f;
}

// ================= prep: bake MADE mask into W3 / transpose b3 =================
__global__ __launch_bounds__(128)
void prep_kernel(const float* __restrict__ W3, const float* __restrict__ b3)
{
  int d = blockIdx.x;
  for (int idx = threadIdx.x; idx < 768; idx += 128){
    int m = idx >> 5, i = idx & 31;
    float v = 0.f;
    if (m < 23 && i < d) v = W3[(m*64 + d)*32 + i];
    g_w3m[d*768 + idx] = v;
  }
  if (threadIdx.x < 24){
    int m = threadIdx.x;
    g_b3t[d*24 + m] = (m < 23) ? b3[m*64 + d] : 0.f;
  }
}

// ================= MADE (frozen, Round-4 proven) =================
#define MR 64
__global__ __launch_bounds__(MR)
void made_kernel(const float* __restrict__ x,
                 const float* __restrict__ W1, const float* __restrict__ b1,
                 const float* __restrict__ W2, const float* __restrict__ b2,
                 int B)
{
  extern __shared__ float smem[];
  float* xs  = smem;            // MR*66
  float* wsh = smem + MR*66;    // 6144 raw W1(4096)+W2(2048)

  const int tid  = threadIdx.x;
  const int row0 = blockIdx.x * MR;

  for (int idx = tid; idx < MR*64; idx += MR)
    xs[(idx>>6)*66 + (idx&63)] = x[(size_t)row0*64 + idx];
  for (int idx = tid; idx < 6144; idx += MR)
    wsh[idx] = (idx < 4096) ? W1[idx] : W2[idx-4096];
  __syncthreads();

  u64 xp[32];
  {
    const u64* xr = (const u64*)(xs + tid*66);
    #pragma unroll
    for (int k=0;k<32;k++) xp[k] = xr[k];
  }

  float h1f[64];
  #pragma unroll
  for (int j = 0; j < 64; j++){
    const int jj = j % 63;
    const float* wrow = wsh + j*64;
    const u64* wr = (const u64*)wrow;
    u64 a0=0ull,a1=0ull,a2=0ull,a3=0ull;
    #pragma unroll
    for (int k = 0; k < 32; k++){
      if (2*k + 1 <= jj){
        if      ((k&3)==0) fma2(a0, xp[k], wr[k]);
        else if ((k&3)==1) fma2(a1, xp[k], wr[k]);
        else if ((k&3)==2) fma2(a2, xp[k], wr[k]);
        else               fma2(a3, xp[k], wr[k]);
      }
    }
    float2 s0=unpk(a0), s1=unpk(a1), s2=unpk(a2), s3=unpk(a3);
    float s = ((s0.x+s0.y)+(s1.x+s1.y)) + ((s2.x+s2.y)+(s3.x+s3.y));
    if ((jj & 1) == 0) s = fmaf(unpk(xp[jj>>1]).x, wrow[jj], s);
    h1f[j] = fmaxf(s + __ldg(b1 + j), 0.f);
  }

  #pragma unroll
  for (int j = 0; j < 32; j++){
    const float* wrow = wsh + 4096 + j*64;
    float a0=0.f,a1=0.f,a2=0.f,a3=0.f;
    #pragma unroll
    for (int i = 0; i < 63; i++){
      if (i <= j){
        if      ((i&3)==0) a0 = fmaf(h1f[i], wrow[i], a0);
        else if ((i&3)==1) a1 = fmaf(h1f[i], wrow[i], a1);
        else if ((i&3)==2) a2 = fmaf(h1f[i], wrow[i], a2);
        else               a3 = fmaf(h1f[i], wrow[i], a3);
      }
    }
    a0 = fmaf(h1f[63], wrow[63], a0);
    float s = ((a0+a1)+(a2+a3)) + __ldg(b2 + j);
    xs[tid*66 + j] = fmaxf(s, 0.f);
  }
  __syncthreads();
  for (int idx = tid; idx < MR*32; idx += MR)
    g_h2[(size_t)row0*32 + idx] = xs[(idx>>5)*66 + (idx&31)];
}

// ================= spline: projection + RQ spline (1 d per thread) =================
template<int KM, int CNT>
__device__ __forceinline__ void pvb(float* o, const u64* h2p,
                                    const float* slab, const float* bb, int m0)
{
  #pragma unroll
  for (int mm = 0; mm < CNT; mm++){
    int m = m0 + mm;
    const ulonglong2* W = (const ulonglong2*)(slab + m*32);
    u64 a0 = 0ull, a1 = 0ull;
    #pragma unroll
    for (int k = 0; k < KM; k++){
      ulonglong2 w = W[k];
      fma2(a0, h2p[2*k],   w.x);
      fma2(a1, h2p[2*k+1], w.y);
    }
    float2 s0 = unpk(a0), s1 = unpk(a1);
    o[mm] = s0.x + s0.y + s1.x + s1.y + bb[m];
  }
}

__device__ __forceinline__ void softmax_cum(const float* v, float* cum)
{
  float mx = v[0];
  #pragma unroll
  for (int k=1;k<8;k++) mx = fmaxf(mx, v[k]);
  float ev[8], s = 0.f;
  #pragma unroll
  for (int k=0;k<8;k++){ ev[k] = __expf(v[k]-mx); s += ev[k]; }
  float inv = __fdividef(1.f, s);
  cum[0] = -3.f; float c = 0.f;
  #pragma unroll
  for (int k=0;k<7;k++){ c += 1e-3f + 0.992f*(ev[k]*inv); cum[k+1] = fmaf(6.f, c, -3.f); }
  cum[8] = 3.f;
}

__device__ __forceinline__ void rq_eval(const float* cumw, const float* cumh,
                                        const float* der, float xv,
                                        float& yo, float& ldo)
{
  float xc = fminf(fmaxf(xv, -3.f), 3.f);
  bool inside = (xv >= -3.f) && (xv <= 3.f);

  int cnt = 0;
  #pragma unroll
  for (int k=0;k<9;k++) cnt += (xc >= cumw[k] + 1e-6f) ? 1 : 0;
  int bi = cnt - 1; bi = bi < 0 ? 0 : (bi > 7 ? 7 : bi);

  float xk = cumw[0], xk1 = cumw[1], yk = cumh[0], yk1 = cumh[1], dk = der[0], dk1 = der[1];
  #pragma unroll
  for (int k=1;k<8;k++){
    bool m = (bi == k);
    xk  = m ? cumw[k]   : xk;   xk1 = m ? cumw[k+1] : xk1;
    yk  = m ? cumh[k]   : yk;   yk1 = m ? cumh[k+1] : yk1;
    dk  = m ? der[k]    : dk;   dk1 = m ? der[k+1]  : dk1;
  }
  float wk = xk1 - xk, hk = yk1 - yk;
  float invwk = __fdividef(1.f, wk);
  float delta = hk * invwk;
  float th  = (xc - xk) * invwk;
  float omt = 1.f - th;
  float tt  = th * omt;
  float th2 = th * th;
  float num = hk * (delta*th2 + dk*tt);
  float den = delta + (dk + dk1 - 2.f*delta) * tt;
  float y   = yk + __fdividef(num, den);
  float dnum = delta*delta * (dk1*th2 + 2.f*delta*tt + dk*omt*omt);
  float ldv  = __logf(__fdividef(dnum, den*den));

  yo  = inside ? y   : xv;
  ldo = inside ? ldv : 0.f;
}

template<int KM>
__device__ __forceinline__ void spline_body(const float* h2row, const float* slab,
                                            const float* bb,
                                            float xv, float& yo, float& ldo)
{
  u64 h2p[2*KM];
  {
    const u64* hp = (const u64*)h2row;
    #pragma unroll
    for (int k = 0; k < 2*KM; k++) h2p[k] = hp[k];
  }

  float t8[8], cumw[9], cumh[9], der[9];
  pvb<KM,8>(t8, h2p, slab, bb, 0);
  softmax_cum(t8, cumw);
  pvb<KM,8>(t8, h2p, slab, bb, 8);
  softmax_cum(t8, cumh);
  pvb<KM,7>(t8, h2p, slab, bb, 16);
  der[0] = 1.f; der[8] = 1.f;
  #pragma unroll
  for (int k=0;k<7;k++){
    float v = t8[k];
    float sp = fmaxf(v, 0.f) + __logf(1.f + __expf(-fabsf(v)));
    der[k+1] = 1e-3f + sp;
  }

  rq_eval(cumw, cumh, der, xv, yo, ldo);
}

__global__ __launch_bounds__(512, 2)
void spline_kernel(const float* __restrict__ x, float* __restrict__ out, int B)
{
  __shared__ __align__(16) float h2s[128*34];
  __shared__ __align__(16) float slabs[4*768];
  __shared__ float b3s[96];
  __shared__ __align__(16) float zsm[512];
  __shared__ float lsum[512];

  const int tid  = threadIdx.x;
  const int r    = tid & 127;
  const int c    = tid >> 7;             // 0..3 : which d in the group
  const int row0 = blockIdx.x * 128;
  const int g    = blockIdx.y;           // 0..15
  const int D0   = g * 4;
  const int kmax = (g + 1 < 8) ? (g + 1) : 8;

  {
    const float2* src = (const float2*)(g_h2 + (size_t)row0*32);
    #pragma unroll
    for (int it = 0; it < 4; it++){
      int idx = tid + it*512;
      int rr = idx >> 4, cc = idx & 15;
      *(float2*)(h2s + rr*34 + cc*2) = src[idx];
    }
  }
  {
    const float4* src = (const float4*)(g_w3m + D0*768);
    float4* dst = (float4*)slabs;
    dst[tid] = src[tid];
    if (tid < 256) dst[tid + 512] = src[tid + 512];
  }
  if (tid < 96) b3s[tid] = g_b3t[D0*24 + tid];
  __syncthreads();

  const float* h2row = h2s + r*34;
  const float* slab  = slabs + c*768;
  const float* bb    = b3s + c*24;
  float xv = x[(size_t)(row0 + r)*64 + D0 + c];
  float yo, ldo;

  switch (kmax){
    case 1: spline_body<1>(h2row, slab, bb, xv, yo, ldo); break;
    case 2: spline_body<2>(h2row, slab, bb, xv, yo, ldo); break;
    case 3: spline_body<3>(h2row, slab, bb, xv, yo, ldo); break;
    case 4: spline_body<4>(h2row, slab, bb, xv, yo, ldo); break;
    case 5: spline_body<5>(h2row, slab, bb, xv, yo, ldo); break;
    case 6: spline_body<6>(h2row, slab, bb, xv, yo, ldo); break;
    case 7: spline_body<7>(h2row, slab, bb, xv, yo, ldo); break;
    default: spline_body<8>(h2row, slab, bb, xv, yo, ldo); break;
  }

  zsm[r*4 + c] = yo;
  lsum[tid] = ldo;
  __syncthreads();

  if (tid < 128){
    float4 v = *(const float4*)(zsm + tid*4);
    *(float4*)(out + (size_t)(row0 + tid)*64 + D0) = v;
    g_ldp[(size_t)g*B + row0 + tid] =
      (lsum[tid] + lsum[tid + 128]) + (lsum[tid + 256] + lsum[tid + 384]);
  }
}

// ================= log-det reduction =================
__global__ __launch_bounds__(128)
void reduce_kernel(float* __restrict__ out, int B)
{
  int r = blockIdx.x*128 + threadIdx.x;
  float s = 0.f;
  #pragma unroll
  for (int g = 0; g < 16; g++) s += g_ldp[(size_t)g*B + r];
  out[(size_t)B*64 + r] = s;
}

// ================= launch =================
extern "C" void kernel_launch(void* const* d_in, const int* in_sizes, int n_in,
                              void* d_out, int out_size)
{
  const float* x  = (const float*)d_in[0];
  const float* W1 = (const float*)d_in[1];
  const float* b1 = (const float*)d_in[2];
  const float* W2 = (const float*)d_in[3];
  const float* b2 = (const float*)d_in[4];
  const float* W3 = (const float*)d_in[5];
  const float* b3 = (const float*)d_in[6];
  float* out = (float*)d_out;

  int B = in_sizes[0] / 64;
  int smemA = (MR*66 + 6144) * (int)sizeof(float);   // 41472

  cudaFuncSetAttribute(made_kernel,
                       cudaFuncAttributeMaxDynamicSharedMemorySize, smemA);

  prep_kernel<<<64, 128>>>(W3, b3);
  made_kernel<<<B/MR, MR, smemA>>>(x, W1, b1, W2, b2, B);
  spline_kernel<<<dim3(B/128, 16), 512>>>(x, out, B);
  reduce_kernel<<<B/128, 128>>>(out, B);
}

// round 11
// speedup vs baseline: 1.0865x; 1.0865x over previous
#include <cuda_runtime.h>

typedef unsigned long long u64;

__device__ float g_h2[32768 * 32];
__device__ float g_w3m[64 * 768];
__device__ float g_b3t[64 * 24];

__device__ __forceinline__ void fma2(u64 &acc, u64 a, u64 b){
  asm("fma.rn.f32x2 %0, %1, %2, %0;" : "+l"(acc) : "l"(a), "l"(b));
}
__device__ __forceinline__ float2 unpk(u64 v){
  float2 f; asm("mov.b64 {%0,%1}, %2;" : "=f"(f.x), "=f"(f.y) : "l"(v)); return f;
}

// ================= prep: bake MADE mask into W3 / transpose b3 =================
__global__ __launch_bounds__(128)
void prep_kernel(const float* __restrict__ W3, const float* __restrict__ b3)
{
  int d = blockIdx.x;
  for (int idx = threadIdx.x; idx < 768; idx += 128){
    int m = idx >> 5, i = idx & 31;
    float v = 0.f;
    if (m < 23 && i < d) v = W3[(m*64 + d)*32 + i];
    g_w3m[d*768 + idx] = v;
  }
  if (threadIdx.x < 24){
    int m = threadIdx.x;
    g_b3t[d*24 + m] = (m < 23) ? b3[m*64 + d] : 0.f;
  }
}

// ================= MADE (frozen, Round-4 proven) =================
#define MR 64
__global__ __launch_bounds__(MR)
void made_kernel(const float* __restrict__ x,
                 const float* __restrict__ W1, const float* __restrict__ b1,
                 const float* __restrict__ W2, const float* __restrict__ b2,
                 int B)
{
  extern __shared__ float smem[];
  float* xs  = smem;            // MR*66
  float* wsh = smem + MR*66;    // 6144 raw W1(4096)+W2(2048)

  const int tid  = threadIdx.x;
  const int row0 = blockIdx.x * MR;

  for (int idx = tid; idx < MR*64; idx += MR)
    xs[(idx>>6)*66 + (idx&63)] = x[(size_t)row0*64 + idx];
  for (int idx = tid; idx < 6144; idx += MR)
    wsh[idx] = (idx < 4096) ? W1[idx] : W2[idx-4096];
  __syncthreads();

  u64 xp[32];
  {
    const u64* xr = (const u64*)(xs + tid*66);
    #pragma unroll
    for (int k=0;k<32;k++) xp[k] = xr[k];
  }

  float h1f[64];
  #pragma unroll
  for (int j = 0; j < 64; j++){
    const int jj = j % 63;
    const float* wrow = wsh + j*64;
    const u64* wr = (const u64*)wrow;
    u64 a0=0ull,a1=0ull,a2=0ull,a3=0ull;
    #pragma unroll
    for (int k = 0; k < 32; k++){
      if (2*k + 1 <= jj){
        if      ((k&3)==0) fma2(a0, xp[k], wr[k]);
        else if ((k&3)==1) fma2(a1, xp[k], wr[k]);
        else if ((k&3)==2) fma2(a2, xp[k], wr[k]);
        else               fma2(a3, xp[k], wr[k]);
      }
    }
    float2 s0=unpk(a0), s1=unpk(a1), s2=unpk(a2), s3=unpk(a3);
    float s = ((s0.x+s0.y)+(s1.x+s1.y)) + ((s2.x+s2.y)+(s3.x+s3.y));
    if ((jj & 1) == 0) s = fmaf(unpk(xp[jj>>1]).x, wrow[jj], s);
    h1f[j] = fmaxf(s + __ldg(b1 + j), 0.f);
  }

  #pragma unroll
  for (int j = 0; j < 32; j++){
    const float* wrow = wsh + 4096 + j*64;
    float a0=0.f,a1=0.f,a2=0.f,a3=0.f;
    #pragma unroll
    for (int i = 0; i < 63; i++){
      if (i <= j){
        if      ((i&3)==0) a0 = fmaf(h1f[i], wrow[i], a0);
        else if ((i&3)==1) a1 = fmaf(h1f[i], wrow[i], a1);
        else if ((i&3)==2) a2 = fmaf(h1f[i], wrow[i], a2);
        else               a3 = fmaf(h1f[i], wrow[i], a3);
      }
    }
    a0 = fmaf(h1f[63], wrow[63], a0);
    float s = ((a0+a1)+(a2+a3)) + __ldg(b2 + j);
    xs[tid*66 + j] = fmaxf(s, 0.f);
  }
  __syncthreads();
  for (int idx = tid; idx < MR*32; idx += MR)
    g_h2[(size_t)row0*32 + idx] = xs[(idx>>5)*66 + (idx&31)];
}

// ================= spline: projection + RQ spline (Round-7 proven body) =================
template<int KM, int CNT>
__device__ __forceinline__ void pvb(float* o, const u64* h2p,
                                    const float* slab, const float* bb, int m0)
{
  #pragma unroll
  for (int mm = 0; mm < CNT; mm++){
    int m = m0 + mm;
    const ulonglong2* W = (const ulonglong2*)(slab + m*32);
    u64 a0 = 0ull, a1 = 0ull;
    #pragma unroll
    for (int k = 0; k < KM; k++){
      ulonglong2 w = W[k];
      fma2(a0, h2p[2*k],   w.x);
      fma2(a1, h2p[2*k+1], w.y);
    }
    float2 s0 = unpk(a0), s1 = unpk(a1);
    o[mm] = s0.x + s0.y + s1.x + s1.y + bb[m];
  }
}

__device__ __forceinline__ void softmax_cum(const float* v, float* cum)
{
  float mx = v[0];
  #pragma unroll
  for (int k=1;k<8;k++) mx = fmaxf(mx, v[k]);
  float ev[8], s = 0.f;
  #pragma unroll
  for (int k=0;k<8;k++){ ev[k] = __expf(v[k]-mx); s += ev[k]; }
  float inv = 1.0f / s;
  cum[0] = -3.f; float c = 0.f;
  #pragma unroll
  for (int k=0;k<7;k++){ c += 1e-3f + 0.992f*(ev[k]*inv); cum[k+1] = fmaf(6.f, c, -3.f); }
  cum[8] = 3.f;
}

__device__ __forceinline__ void rq_eval(const float* cumw, const float* cumh,
                                        const float* der, float xv,
                                        float& yo, float& ldo)
{
  float xc = fminf(fmaxf(xv, -3.f), 3.f);
  bool inside = (xv >= -3.f) && (xv <= 3.f);

  int cnt = 0;
  #pragma unroll
  for (int k=0;k<9;k++) cnt += (xc >= cumw[k] + 1e-6f) ? 1 : 0;
  int bi = cnt - 1; bi = bi < 0 ? 0 : (bi > 7 ? 7 : bi);

  float xk = cumw[0], xk1 = cumw[1], yk = cumh[0], yk1 = cumh[1], dk = der[0], dk1 = der[1];
  #pragma unroll
  for (int k=1;k<8;k++){
    bool m = (bi == k);
    xk  = m ? cumw[k]   : xk;   xk1 = m ? cumw[k+1] : xk1;
    yk  = m ? cumh[k]   : yk;   yk1 = m ? cumh[k+1] : yk1;
    dk  = m ? der[k]    : dk;   dk1 = m ? der[k+1]  : dk1;
  }
  float wk = xk1 - xk, hk = yk1 - yk;
  float invwk = 1.0f / wk;
  float delta = hk * invwk;
  float th  = (xc - xk) * invwk;
  float omt = 1.f - th;
  float tt  = th * omt;
  float th2 = th * th;
  float num = hk * (delta*th2 + dk*tt);
  float den = delta + (dk + dk1 - 2.f*delta) * tt;
  float y   = yk + num / den;
  float dnum = delta*delta * (dk1*th2 + 2.f*delta*tt + dk*omt*omt);
  float ldv  = __logf(dnum) - 2.f*__logf(den);

  yo  = inside ? y   : xv;
  ldo = inside ? ldv : 0.f;
}

template<int KM>
__device__ __forceinline__ void spline_body(const float* h2row, const float* slabs,
                                            const float* b3s, int ds,
                                            const float* xin, float* y2, float& ldacc)
{
  u64 h2p[2*KM];
  {
    const u64* hp = (const u64*)h2row;
    #pragma unroll
    for (int k = 0; k < 2*KM; k++) h2p[k] = hp[k];
  }
  #pragma unroll
  for (int p = 0; p < 2; p++){
    const int c = ds*2 + p;
    const float* slab = slabs + c*768;
    const float* bb   = b3s + c*24;

    float t8[8], cumw[9], cumh[9], der[9];
    pvb<KM,8>(t8, h2p, slab, bb, 0);
    softmax_cum(t8, cumw);
    pvb<KM,8>(t8, h2p, slab, bb, 8);
    softmax_cum(t8, cumh);
    pvb<KM,7>(t8, h2p, slab, bb, 16);
    der[0] = 1.f; der[8] = 1.f;
    #pragma unroll
    for (int k=0;k<7;k++){
      float v = t8[k];
      float sp = fmaxf(v, 0.f) + __logf(1.f + __expf(-fabsf(v)));
      der[k+1] = 1e-3f + sp;
    }

    float yo, ldo;
    rq_eval(cumw, cumh, der, xin[p], yo, ldo);
    y2[p] = yo;
    ldacc += ldo;
  }
}

__global__ __launch_bounds__(256, 3)
void spline_kernel(const float* __restrict__ x, float* __restrict__ out, int B)
{
  __shared__ __align__(16) float h2s[128*34];
  __shared__ __align__(16) float slabs[4*768];
  __shared__ float b3s[96];
  __shared__ __align__(16) float zsm[512];
  __shared__ float lsum[256];

  const int tid  = threadIdx.x;
  const int r    = tid & 127;
  const int ds   = tid >> 7;
  const int row0 = blockIdx.x * 128;
  const int g    = blockIdx.y;
  const int D0   = g * 4;
  const int kmax = (g + 1 < 8) ? (g + 1) : 8;

  {
    const float2* src = (const float2*)(g_h2 + (size_t)row0*32);
    #pragma unroll
    for (int it = 0; it < 8; it++){
      int idx = tid + it*256;
      int rr = idx >> 4, cc = idx & 15;
      *(float2*)(h2s + rr*34 + cc*2) = src[idx];
    }
  }
  {
    const float4* src = (const float4*)(g_w3m + D0*768);
    float4* dst = (float4*)slabs;
    #pragma unroll
    for (int it = 0; it < 3; it++) dst[tid + it*256] = src[tid + it*256];
  }
  if (tid < 96) b3s[tid] = g_b3t[D0*24 + tid];
  __syncthreads();

  float2 xv2 = *(const float2*)(x + (size_t)(row0 + r)*64 + D0 + ds*2);
  float xin[2] = {xv2.x, xv2.y};
  float y2[2];
  float ldacc = 0.f;
  const float* h2row = h2s + r*34;

  switch (kmax){
    case 1: spline_body<1>(h2row, slabs, b3s, ds, xin, y2, ldacc); break;
    case 2: spline_body<2>(h2row, slabs, b3s, ds, xin, y2, ldacc); break;
    case 3: spline_body<3>(h2row, slabs, b3s, ds, xin, y2, ldacc); break;
    case 4: spline_body<4>(h2row, slabs, b3s, ds, xin, y2, ldacc); break;
    case 5: spline_body<5>(h2row, slabs, b3s, ds, xin, y2, ldacc); break;
    case 6: spline_body<6>(h2row, slabs, b3s, ds, xin, y2, ldacc); break;
    case 7: spline_body<7>(h2row, slabs, b3s, ds, xin, y2, ldacc); break;
    default: spline_body<8>(h2row, slabs, b3s, ds, xin, y2, ldacc); break;
  }

  zsm[r*4 + ds*2 + 0] = y2[0];
  zsm[r*4 + ds*2 + 1] = y2[1];
  lsum[tid] = ldacc;
  __syncthreads();

  if (tid < 128){
    float4 v = *(const float4*)(zsm + tid*4);
    *(float4*)(out + (size_t)(row0 + tid)*64 + D0) = v;
    // fused log-det reduction: one REDG per row per d-group
    atomicAdd(out + (size_t)B*64 + row0 + tid, lsum[tid] + lsum[tid + 128]);
  }
}

// ================= launch =================
extern "C" void kernel_launch(void* const* d_in, const int* in_sizes, int n_in,
                              void* d_out, int out_size)
{
  const float* x  = (const float*)d_in[0];
  const float* W1 = (const float*)d_in[1];
  const float* b1 = (const float*)d_in[2];
  const float* W2 = (const float*)d_in[3];
  const float* b2 = (const float*)d_in[4];
  const float* W3 = (const float*)d_in[5];
  const float* b3 = (const float*)d_in[6];
  float* out = (float*)d_out;

  int B = in_sizes[0] / 64;
  int smemA = (MR*66 + 6144) * (int)sizeof(float);   // 41472

  cudaFuncSetAttribute(made_kernel,
                       cudaFuncAttributeMaxDynamicSharedMemorySize, smemA);

  // zero the log-det accumulator region (graph-capturable async memset)
  cudaMemsetAsync(out + (size_t)B*64, 0, (size_t)B * sizeof(float));

  prep_kernel<<<64, 128>>>(W3, b3);
  made_kernel<<<B/MR, MR, smemA>>>(x, W1, b1, W2, b2, B);
  spline_kernel<<<dim3(B/128, 16), 256>>>(x, out, B);
}

// round 12
// speedup vs baseline: 1.1040x; 1.0161x over previous
#include <cuda_runtime.h>

typedef unsigned long long u64;

__device__ float g_h2[32768 * 32];

__device__ __forceinline__ void fma2(u64 &acc, u64 a, u64 b){
  asm("fma.rn.f32x2 %0, %1, %2, %0;" : "+l"(acc) : "l"(a), "l"(b));
}
__device__ __forceinline__ float2 unpk(u64 v){
  float2 f; asm("mov.b64 {%0,%1}, %2;" : "=f"(f.x), "=f"(f.y) : "l"(v)); return f;
}

// ================= MADE (frozen, Round-4 proven) =================
#define MR 64
__global__ __launch_bounds__(MR)
void made_kernel(const float* __restrict__ x,
                 const float* __restrict__ W1, const float* __restrict__ b1,
                 const float* __restrict__ W2, const float* __restrict__ b2,
                 int B)
{
  extern __shared__ float smem[];
  float* xs  = smem;            // MR*66
  float* wsh = smem + MR*66;    // 6144 raw W1(4096)+W2(2048)

  const int tid  = threadIdx.x;
  const int row0 = blockIdx.x * MR;

  for (int idx = tid; idx < MR*64; idx += MR)
    xs[(idx>>6)*66 + (idx&63)] = x[(size_t)row0*64 + idx];
  for (int idx = tid; idx < 6144; idx += MR)
    wsh[idx] = (idx < 4096) ? W1[idx] : W2[idx-4096];
  __syncthreads();

  u64 xp[32];
  {
    const u64* xr = (const u64*)(xs + tid*66);
    #pragma unroll
    for (int k=0;k<32;k++) xp[k] = xr[k];
  }

  float h1f[64];
  #pragma unroll
  for (int j = 0; j < 64; j++){
    const int jj = j % 63;
    const float* wrow = wsh + j*64;
    const u64* wr = (const u64*)wrow;
    u64 a0=0ull,a1=0ull,a2=0ull,a3=0ull;
    #pragma unroll
    for (int k = 0; k < 32; k++){
      if (2*k + 1 <= jj){
        if      ((k&3)==0) fma2(a0, xp[k], wr[k]);
        else if ((k&3)==1) fma2(a1, xp[k], wr[k]);
        else if ((k&3)==2) fma2(a2, xp[k], wr[k]);
        else               fma2(a3, xp[k], wr[k]);
      }
    }
    float2 s0=unpk(a0), s1=unpk(a1), s2=unpk(a2), s3=unpk(a3);
    float s = ((s0.x+s0.y)+(s1.x+s1.y)) + ((s2.x+s2.y)+(s3.x+s3.y));
    if ((jj & 1) == 0) s = fmaf(unpk(xp[jj>>1]).x, wrow[jj], s);
    h1f[j] = fmaxf(s + __ldg(b1 + j), 0.f);
  }

  #pragma unroll
  for (int j = 0; j < 32; j++){
    const float* wrow = wsh + 4096 + j*64;
    float a0=0.f,a1=0.f,a2=0.f,a3=0.f;
    #pragma unroll
    for (int i = 0; i < 63; i++){
      if (i <= j){
        if      ((i&3)==0) a0 = fmaf(h1f[i], wrow[i], a0);
        else if ((i&3)==1) a1 = fmaf(h1f[i], wrow[i], a1);
        else if ((i&3)==2) a2 = fmaf(h1f[i], wrow[i], a2);
        else               a3 = fmaf(h1f[i], wrow[i], a3);
      }
    }
    a0 = fmaf(h1f[63], wrow[63], a0);
    float s = ((a0+a1)+(a2+a3)) + __ldg(b2 + j);
    xs[tid*66 + j] = fmaxf(s, 0.f);
  }
  __syncthreads();
  for (int idx = tid; idx < MR*32; idx += MR)
    g_h2[(size_t)row0*32 + idx] = xs[(idx>>5)*66 + (idx&31)];
}

// ================= spline: projection + RQ spline (Round-7 proven body) =================
template<int KM, int CNT>
__device__ __forceinline__ void pvb(float* o, const u64* h2p,
                                    const float* slab, const float* bb, int m0)
{
  #pragma unroll
  for (int mm = 0; mm < CNT; mm++){
    int m = m0 + mm;
    const ulonglong2* W = (const ulonglong2*)(slab + m*32);
    u64 a0 = 0ull, a1 = 0ull;
    #pragma unroll
    for (int k = 0; k < KM; k++){
      ulonglong2 w = W[k];
      fma2(a0, h2p[2*k],   w.x);
      fma2(a1, h2p[2*k+1], w.y);
    }
    float2 s0 = unpk(a0), s1 = unpk(a1);
    o[mm] = s0.x + s0.y + s1.x + s1.y + bb[m];
  }
}

__device__ __forceinline__ void softmax_cum(const float* v, float* cum)
{
  float mx = v[0];
  #pragma unroll
  for (int k=1;k<8;k++) mx = fmaxf(mx, v[k]);
  float ev[8], s = 0.f;
  #pragma unroll
  for (int k=0;k<8;k++){ ev[k] = __expf(v[k]-mx); s += ev[k]; }
  float inv = 1.0f / s;
  cum[0] = -3.f; float c = 0.f;
  #pragma unroll
  for (int k=0;k<7;k++){ c += 1e-3f + 0.992f*(ev[k]*inv); cum[k+1] = fmaf(6.f, c, -3.f); }
  cum[8] = 3.f;
}

__device__ __forceinline__ void rq_eval(const float* cumw, const float* cumh,
                                        const float* der, float xv,
                                        float& yo, float& ldo)
{
  float xc = fminf(fmaxf(xv, -3.f), 3.f);
  bool inside = (xv >= -3.f) && (xv <= 3.f);

  int cnt = 0;
  #pragma unroll
  for (int k=0;k<9;k++) cnt += (xc >= cumw[k] + 1e-6f) ? 1 : 0;
  int bi = cnt - 1; bi = bi < 0 ? 0 : (bi > 7 ? 7 : bi);

  float xk = cumw[0], xk1 = cumw[1], yk = cumh[0], yk1 = cumh[1], dk = der[0], dk1 = der[1];
  #pragma unroll
  for (int k=1;k<8;k++){
    bool m = (bi == k);
    xk  = m ? cumw[k]   : xk;   xk1 = m ? cumw[k+1] : xk1;
    yk  = m ? cumh[k]   : yk;   yk1 = m ? cumh[k+1] : yk1;
    dk  = m ? der[k]    : dk;   dk1 = m ? der[k+1]  : dk1;
  }
  float wk = xk1 - xk, hk = yk1 - yk;
  float invwk = 1.0f / wk;
  float delta = hk * invwk;
  float th  = (xc - xk) * invwk;
  float omt = 1.f - th;
  float tt  = th * omt;
  float th2 = th * th;
  float num = hk * (delta*th2 + dk*tt);
  float den = delta + (dk + dk1 - 2.f*delta) * tt;
  float y   = yk + num / den;
  float dnum = delta*delta * (dk1*th2 + 2.f*delta*tt + dk*omt*omt);
  float ldv  = __logf(dnum) - 2.f*__logf(den);

  yo  = inside ? y   : xv;
  ldo = inside ? ldv : 0.f;
}

template<int KM>
__device__ __forceinline__ void spline_body(const float* h2row, const float* slabs,
                                            const float* b3s, int ds,
                                            const float* xin, float* y2, float& ldacc)
{
  u64 h2p[2*KM];
  {
    const u64* hp = (const u64*)h2row;
    #pragma unroll
    for (int k = 0; k < 2*KM; k++) h2p[k] = hp[k];
  }
  #pragma unroll
  for (int p = 0; p < 2; p++){
    const int c = ds*2 + p;
    const float* slab = slabs + c*768;
    const float* bb   = b3s + c*24;

    float t8[8], cumw[9], cumh[9], der[9];
    pvb<KM,8>(t8, h2p, slab, bb, 0);
    softmax_cum(t8, cumw);
    pvb<KM,8>(t8, h2p, slab, bb, 8);
    softmax_cum(t8, cumh);
    pvb<KM,7>(t8, h2p, slab, bb, 16);
    der[0] = 1.f; der[8] = 1.f;
    #pragma unroll
    for (int k=0;k<7;k++){
      float v = t8[k];
      float sp = fmaxf(v, 0.f) + __logf(1.f + __expf(-fabsf(v)));
      der[k+1] = 1e-3f + sp;
    }

    float yo, ldo;
    rq_eval(cumw, cumh, der, xin[p], yo, ldo);
    y2[p] = yo;
    ldacc += ldo;
  }
}

__global__ __launch_bounds__(256, 3)
void spline_kernel(const float* __restrict__ x,
                   const float* __restrict__ W3, const float* __restrict__ b3,
                   float* __restrict__ out, int B)
{
  __shared__ __align__(16) float h2s[128*34];
  __shared__ __align__(16) float slabs[4*768];
  __shared__ float b3s[96];
  __shared__ __align__(16) float zsm[512];
  __shared__ float lsum[256];

  const int tid  = threadIdx.x;
  const int r    = tid & 127;
  const int ds   = tid >> 7;
  const int row0 = blockIdx.x * 128;
  const int g    = blockIdx.y;
  const int D0   = g * 4;
  const int kmax = (g + 1 < 8) ? (g + 1) : 8;

  // stage h2 tile
  {
    const float2* src = (const float2*)(g_h2 + (size_t)row0*32);
    #pragma unroll
    for (int it = 0; it < 8; it++){
      int idx = tid + it*256;
      int rr = idx >> 4, cc = idx & 15;
      *(float2*)(h2s + rr*34 + cc*2) = src[idx];
    }
  }
  // stage 4 W3 slabs directly from raw W3, applying the MADE mask inline
  #pragma unroll
  for (int it = 0; it < 12; it++){
    int idx = tid + it*256;          // 0..3071
    int dt  = idx / 768;
    int rem = idx - dt*768;
    int m   = rem >> 5, i = rem & 31;
    int d   = D0 + dt;
    float v = 0.f;
    if (m < 23 && i < d) v = __ldg(W3 + (m*64 + d)*32 + i);
    slabs[idx] = v;
  }
  if (tid < 96){
    int dt = tid / 24, m = tid % 24;
    b3s[tid] = (m < 23) ? __ldg(b3 + m*64 + D0 + dt) : 0.f;
  }
  __syncthreads();

  float2 xv2 = *(const float2*)(x + (size_t)(row0 + r)*64 + D0 + ds*2);
  float xin[2] = {xv2.x, xv2.y};
  float y2[2];
  float ldacc = 0.f;
  const float* h2row = h2s + r*34;

  switch (kmax){
    case 1: spline_body<1>(h2row, slabs, b3s, ds, xin, y2, ldacc); break;
    case 2: spline_body<2>(h2row, slabs, b3s, ds, xin, y2, ldacc); break;
    case 3: spline_body<3>(h2row, slabs, b3s, ds, xin, y2, ldacc); break;
    case 4: spline_body<4>(h2row, slabs, b3s, ds, xin, y2, ldacc); break;
    case 5: spline_body<5>(h2row, slabs, b3s, ds, xin, y2, ldacc); break;
    case 6: spline_body<6>(h2row, slabs, b3s, ds, xin, y2, ldacc); break;
    case 7: spline_body<7>(h2row, slabs, b3s, ds, xin, y2, ldacc); break;
    default: spline_body<8>(h2row, slabs, b3s, ds, xin, y2, ldacc); break;
  }

  zsm[r*4 + ds*2 + 0] = y2[0];
  zsm[r*4 + ds*2 + 1] = y2[1];
  lsum[tid] = ldacc;
  __syncthreads();

  if (tid < 128){
    float4 v = *(const float4*)(zsm + tid*4);
    *(float4*)(out + (size_t)(row0 + tid)*64 + D0) = v;
    atomicAdd(out + (size_t)B*64 + row0 + tid, lsum[tid] + lsum[tid + 128]);
  }
}

// ================= launch =================
extern "C" void kernel_launch(void* const* d_in, const int* in_sizes, int n_in,
                              void* d_out, int out_size)
{
  const float* x  = (const float*)d_in[0];
  const float* W1 = (const float*)d_in[1];
  const float* b1 = (const float*)d_in[2];
  const float* W2 = (const float*)d_in[3];
  const float* b2 = (const float*)d_in[4];
  const float* W3 = (const float*)d_in[5];
  const float* b3 = (const float*)d_in[6];
  float* out = (float*)d_out;

  int B = in_sizes[0] / 64;
  int smemA = (MR*66 + 6144) * (int)sizeof(float);   // 41472

  cudaFuncSetAttribute(made_kernel,
                       cudaFuncAttributeMaxDynamicSharedMemorySize, smemA);

  // zero the log-det accumulator region (graph-capturable async memset)
  cudaMemsetAsync(out + (size_t)B*64, 0, (size_t)B * sizeof(float));

  made_kernel<<<B/MR, MR, smemA>>>(x, W1, b1, W2, b2, B);
  spline_kernel<<<dim3(B/128, 16), 256>>>(x, W3, b3, out, B);
}

// round 13
// speedup vs baseline: 1.1058x; 1.0016x over previous
#include <cuda_runtime.h>

typedef unsigned long long u64;

__device__ float g_h2[32768 * 32];

__device__ __forceinline__ void fma2(u64 &acc, u64 a, u64 b){
  asm("fma.rn.f32x2 %0, %1, %2, %0;" : "+l"(acc) : "l"(a), "l"(b));
}
__device__ __forceinline__ float2 unpk(u64 v){
  float2 f; asm("mov.b64 {%0,%1}, %2;" : "=f"(f.x), "=f"(f.y) : "l"(v)); return f;
}

// ================= MADE (frozen, Round-4 proven) =================
#define MR 64
__global__ __launch_bounds__(MR)
void made_kernel(const float* __restrict__ x,
                 const float* __restrict__ W1, const float* __restrict__ b1,
                 const float* __restrict__ W2, const float* __restrict__ b2,
                 int B)
{
  extern __shared__ float smem[];
  float* xs  = smem;            // MR*66
  float* wsh = smem + MR*66;    // 6144 raw W1(4096)+W2(2048)

  const int tid  = threadIdx.x;
  const int row0 = blockIdx.x * MR;

  for (int idx = tid; idx < MR*64; idx += MR)
    xs[(idx>>6)*66 + (idx&63)] = x[(size_t)row0*64 + idx];
  for (int idx = tid; idx < 6144; idx += MR)
    wsh[idx] = (idx < 4096) ? W1[idx] : W2[idx-4096];
  __syncthreads();

  u64 xp[32];
  {
    const u64* xr = (const u64*)(xs + tid*66);
    #pragma unroll
    for (int k=0;k<32;k++) xp[k] = xr[k];
  }

  float h1f[64];
  #pragma unroll
  for (int j = 0; j < 64; j++){
    const int jj = j % 63;
    const float* wrow = wsh + j*64;
    const u64* wr = (const u64*)wrow;
    u64 a0=0ull,a1=0ull,a2=0ull,a3=0ull;
    #pragma unroll
    for (int k = 0; k < 32; k++){
      if (2*k + 1 <= jj){
        if      ((k&3)==0) fma2(a0, xp[k], wr[k]);
        else if ((k&3)==1) fma2(a1, xp[k], wr[k]);
        else if ((k&3)==2) fma2(a2, xp[k], wr[k]);
        else               fma2(a3, xp[k], wr[k]);
      }
    }
    float2 s0=unpk(a0), s1=unpk(a1), s2=unpk(a2), s3=unpk(a3);
    float s = ((s0.x+s0.y)+(s1.x+s1.y)) + ((s2.x+s2.y)+(s3.x+s3.y));
    if ((jj & 1) == 0) s = fmaf(unpk(xp[jj>>1]).x, wrow[jj], s);
    h1f[j] = fmaxf(s + __ldg(b1 + j), 0.f);
  }

  #pragma unroll
  for (int j = 0; j < 32; j++){
    const float* wrow = wsh + 4096 + j*64;
    float a0=0.f,a1=0.f,a2=0.f,a3=0.f;
    #pragma unroll
    for (int i = 0; i < 63; i++){
      if (i <= j){
        if      ((i&3)==0) a0 = fmaf(h1f[i], wrow[i], a0);
        else if ((i&3)==1) a1 = fmaf(h1f[i], wrow[i], a1);
        else if ((i&3)==2) a2 = fmaf(h1f[i], wrow[i], a2);
        else               a3 = fmaf(h1f[i], wrow[i], a3);
      }
    }
    a0 = fmaf(h1f[63], wrow[63], a0);
    float s = ((a0+a1)+(a2+a3)) + __ldg(b2 + j);
    xs[tid*66 + j] = fmaxf(s, 0.f);
  }
  __syncthreads();
  for (int idx = tid; idx < MR*32; idx += MR)
    g_h2[(size_t)row0*32 + idx] = xs[(idx>>5)*66 + (idx&31)];
}

// ================= spline: row-pair projection + RQ spline =================
template<int KM, int CNT>
__device__ __forceinline__ void pvb2(float* oA, float* oB,
                                     const u64* hA, const u64* hB,
                                     const float* slab, const float* bb, int m0)
{
  #pragma unroll
  for (int mm = 0; mm < CNT; mm++){
    int m = m0 + mm;
    const ulonglong2* W = (const ulonglong2*)(slab + m*32);
    u64 aA0 = 0ull, aA1 = 0ull, aB0 = 0ull, aB1 = 0ull;
    #pragma unroll
    for (int k = 0; k < KM; k++){
      ulonglong2 w = W[k];                    // one broadcast LDS.128 ...
      fma2(aA0, hA[2*k],   w.x);              // ... feeds 4 FFMA2
      fma2(aA1, hA[2*k+1], w.y);
      fma2(aB0, hB[2*k],   w.x);
      fma2(aB1, hB[2*k+1], w.y);
    }
    float2 sA0 = unpk(aA0), sA1 = unpk(aA1);
    float2 sB0 = unpk(aB0), sB1 = unpk(aB1);
    float b = bb[m];
    oA[mm] = sA0.x + sA0.y + sA1.x + sA1.y + b;
    oB[mm] = sB0.x + sB0.y + sB1.x + sB1.y + b;
  }
}

__device__ __forceinline__ void softmax_cum(const float* v, float* cum)
{
  float mx = v[0];
  #pragma unroll
  for (int k=1;k<8;k++) mx = fmaxf(mx, v[k]);
  float ev[8], s = 0.f;
  #pragma unroll
  for (int k=0;k<8;k++){ ev[k] = __expf(v[k]-mx); s += ev[k]; }
  float inv = 1.0f / s;
  cum[0] = -3.f; float c = 0.f;
  #pragma unroll
  for (int k=0;k<7;k++){ c += 1e-3f + 0.992f*(ev[k]*inv); cum[k+1] = fmaf(6.f, c, -3.f); }
  cum[8] = 3.f;
}

__device__ __forceinline__ void rq_eval(const float* cumw, const float* cumh,
                                        const float* der, float xv,
                                        float& yo, float& ldo)
{
  float xc = fminf(fmaxf(xv, -3.f), 3.f);
  bool inside = (xv >= -3.f) && (xv <= 3.f);

  int cnt = 0;
  #pragma unroll
  for (int k=0;k<9;k++) cnt += (xc >= cumw[k] + 1e-6f) ? 1 : 0;
  int bi = cnt - 1; bi = bi < 0 ? 0 : (bi > 7 ? 7 : bi);

  float xk = cumw[0], xk1 = cumw[1], yk = cumh[0], yk1 = cumh[1], dk = der[0], dk1 = der[1];
  #pragma unroll
  for (int k=1;k<8;k++){
    bool m = (bi == k);
    xk  = m ? cumw[k]   : xk;   xk1 = m ? cumw[k+1] : xk1;
    yk  = m ? cumh[k]   : yk;   yk1 = m ? cumh[k+1] : yk1;
    dk  = m ? der[k]    : dk;   dk1 = m ? der[k+1]  : dk1;
  }
  float wk = xk1 - xk, hk = yk1 - yk;
  float invwk = 1.0f / wk;
  float delta = hk * invwk;
  float th  = (xc - xk) * invwk;
  float omt = 1.f - th;
  float tt  = th * omt;
  float th2 = th * th;
  float num = hk * (delta*th2 + dk*tt);
  float den = delta + (dk + dk1 - 2.f*delta) * tt;
  float y   = yk + num / den;
  float dnum = delta*delta * (dk1*th2 + 2.f*delta*tt + dk*omt*omt);
  float ldv  = __logf(dnum) - 2.f*__logf(den);

  yo  = inside ? y   : xv;
  ldo = inside ? ldv : 0.f;
}

template<int KM>
__device__ __forceinline__ void spline_body2(const float* hA_row, const float* hB_row,
                                             const float* slab, const float* bb,
                                             float xA, float xB,
                                             float& yA, float& ldA,
                                             float& yB, float& ldB)
{
  u64 hA[2*KM], hB[2*KM];
  {
    const u64* pa = (const u64*)hA_row;
    const u64* pb = (const u64*)hB_row;
    #pragma unroll
    for (int k = 0; k < 2*KM; k++){ hA[k] = pa[k]; hB[k] = pb[k]; }
  }

  float tA[8], tB[8];
  float cwA[9], cwB[9], chA[9], chB[9], derA[9], derB[9];

  pvb2<KM,8>(tA, tB, hA, hB, slab, bb, 0);
  softmax_cum(tA, cwA);
  softmax_cum(tB, cwB);

  pvb2<KM,8>(tA, tB, hA, hB, slab, bb, 8);
  softmax_cum(tA, chA);
  softmax_cum(tB, chB);

  pvb2<KM,7>(tA, tB, hA, hB, slab, bb, 16);
  derA[0] = 1.f; derA[8] = 1.f;
  derB[0] = 1.f; derB[8] = 1.f;
  #pragma unroll
  for (int k=0;k<7;k++){
    float vA = tA[k], vB = tB[k];
    derA[k+1] = 1e-3f + fmaxf(vA, 0.f) + __logf(1.f + __expf(-fabsf(vA)));
    derB[k+1] = 1e-3f + fmaxf(vB, 0.f) + __logf(1.f + __expf(-fabsf(vB)));
  }

  rq_eval(cwA, chA, derA, xA, yA, ldA);
  rq_eval(cwB, chB, derB, xB, yB, ldB);
}

__global__ __launch_bounds__(256, 2)
void spline_kernel(const float* __restrict__ x,
                   const float* __restrict__ W3, const float* __restrict__ b3,
                   float* __restrict__ out, int B)
{
  __shared__ __align__(16) float h2s[128*34];
  __shared__ __align__(16) float slabs[4*768];
  __shared__ float b3s[96];
  __shared__ __align__(16) float zsm[512];
  __shared__ float lsum[512];

  const int tid  = threadIdx.x;
  const int rp   = tid & 63;            // row-pair base: rows rp and rp+64
  const int c    = tid >> 6;            // 0..3 : which d of the group
  const int row0 = blockIdx.x * 128;
  const int g    = blockIdx.y;          // 0..15
  const int D0   = g * 4;
  const int kmax = (g + 1 < 8) ? (g + 1) : 8;

  // stage h2 tile
  {
    const float2* src = (const float2*)(g_h2 + (size_t)row0*32);
    #pragma unroll
    for (int it = 0; it < 8; it++){
      int idx = tid + it*256;
      int rr = idx >> 4, cc = idx & 15;
      *(float2*)(h2s + rr*34 + cc*2) = src[idx];
    }
  }
  // stage 4 W3 slabs directly from raw W3, applying the MADE mask inline
  #pragma unroll
  for (int it = 0; it < 12; it++){
    int idx = tid + it*256;          // 0..3071
    int dt  = idx / 768;
    int rem = idx - dt*768;
    int m   = rem >> 5, i = rem & 31;
    int d   = D0 + dt;
    float v = 0.f;
    if (m < 23 && i < d) v = __ldg(W3 + (m*64 + d)*32 + i);
    slabs[idx] = v;
  }
  if (tid < 96){
    int dt = tid / 24, m = tid % 24;
    b3s[tid] = (m < 23) ? __ldg(b3 + m*64 + D0 + dt) : 0.f;
  }
  __syncthreads();

  const float* hA_row = h2s + rp*34;
  const float* hB_row = h2s + (rp + 64)*34;
  const float* slab   = slabs + c*768;
  const float* bb     = b3s + c*24;

  float xA = x[(size_t)(row0 + rp)*64      + D0 + c];
  float xB = x[(size_t)(row0 + rp + 64)*64 + D0 + c];
  float yA, ldA, yB, ldB;

  switch (kmax){
    case 1: spline_body2<1>(hA_row, hB_row, slab, bb, xA, xB, yA, ldA, yB, ldB); break;
    case 2: spline_body2<2>(hA_row, hB_row, slab, bb, xA, xB, yA, ldA, yB, ldB); break;
    case 3: spline_body2<3>(hA_row, hB_row, slab, bb, xA, xB, yA, ldA, yB, ldB); break;
    case 4: spline_body2<4>(hA_row, hB_row, slab, bb, xA, xB, yA, ldA, yB, ldB); break;
    case 5: spline_body2<5>(hA_row, hB_row, slab, bb, xA, xB, yA, ldA, yB, ldB); break;
    case 6: spline_body2<6>(hA_row, hB_row, slab, bb, xA, xB, yA, ldA, yB, ldB); break;
    case 7: spline_body2<7>(hA_row, hB_row, slab, bb, xA, xB, yA, ldA, yB, ldB); break;
    default: spline_body2<8>(hA_row, hB_row, slab, bb, xA, xB, yA, ldA, yB, ldB); break;
  }

  zsm[rp*4 + c]        = yA;
  zsm[(rp + 64)*4 + c] = yB;
  lsum[c*128 + rp]      = ldA;
  lsum[c*128 + rp + 64] = ldB;
  __syncthreads();

  if (tid < 128){
    float4 v = *(const float4*)(zsm + tid*4);
    *(float4*)(out + (size_t)(row0 + tid)*64 + D0) = v;
    float l = (lsum[tid] + lsum[128 + tid]) + (lsum[256 + tid] + lsum[384 + tid]);
    atomicAdd(out + (size_t)B*64 + row0 + tid, l);
  }
}

// ================= launch =================
extern "C" void kernel_launch(void* const* d_in, const int* in_sizes, int n_in,
                              void* d_out, int out_size)
{
  const float* x  = (const float*)d_in[0];
  const float* W1 = (const float*)d_in[1];
  const float* b1 = (const float*)d_in[2];
  const float* W2 = (const float*)d_in[3];
  const float* b2 = (const float*)d_in[4];
  const float* W3 = (const float*)d_in[5];
  const float* b3 = (const float*)d_in[6];
  float* out = (float*)d_out;

  int B = in_sizes[0] / 64;
  int smemA = (MR*66 + 6144) * (int)sizeof(float);   // 41472

  cudaFuncSetAttribute(made_kernel,
                       cudaFuncAttributeMaxDynamicSharedMemorySize, smemA);

  // zero the log-det accumulator region (graph-capturable async memset)
  cudaMemsetAsync(out + (size_t)B*64, 0, (size_t)B * sizeof(float));

  made_kernel<<<B/MR, MR, smemA>>>(x, W1, b1, W2, b2, B);
  spline_kernel<<<dim3(B/128, 16), 256>>>(x, W3, b3, out, B);
}